// round 16
// baseline (speedup 1.0000x reference)
#include <cuda_runtime.h>
#include <cuda_fp16.h>

// B=4, C=64, D=16, H=64, W=64, C8=8, k=38 -> thr = rank-26 ascending of 64
#define EPSBN 1e-5f
typedef unsigned long long ull;

// ---------------- packed f32x2 helpers (fma pipe) ----------------
__device__ __forceinline__ ull pk(float lo, float hi) {
  ull r; asm("mov.b64 %0,{%1,%2};" : "=l"(r) : "f"(lo), "f"(hi)); return r;
}
__device__ __forceinline__ void upk(float& lo, float& hi, ull v) {
  asm("mov.b64 {%0,%1},%2;" : "=f"(lo), "=f"(hi) : "l"(v));
}
__device__ __forceinline__ ull fma2(ull a, ull b, ull c) {
  ull d; asm("fma.rn.f32x2 %0,%1,%2,%3;" : "=l"(d) : "l"(a), "l"(b), "l"(c)); return d;
}
__device__ __forceinline__ float silu_f(float v) {
  return v * (1.0f / (1.0f + __expf(-v)));
}

// ---------------- params ----------------
struct C2 {
  ull w1o[256];   // [c*4+j] = pk(w1t[c][2j], w1t[c][2j+1]), bn2 scale folded
  ull w2o[256];   // [c*4+j] = pk(w2[c][2j], w2[c][2j+1])
  ull b1o[4];     // pk(b1_eff[2j], b1_eff[2j+1])
  float b2[64];
  float alpha;
};
__device__   C2 g_c2;
__constant__ C2 c2;
__device__ __half g_y1[16777216];   // 32MB; linear indexing matches x

// ---------------- kernel 1: depthwise conv + BN + SiLU -> fp16 y1 ----------
// R12/R15 frozen internals; d_base selects an 8-deep half (2048 blocks).
#define PITCH 76
__global__ void __launch_bounds__(256)
k_dwconv(const float* __restrict__ x,
         const float* __restrict__ wdw,
         const float* __restrict__ g1, const float* __restrict__ be1,
         const float* __restrict__ m1, const float* __restrict__ v1,
         const float* __restrict__ wp1, const float* __restrict__ bp1,
         const float* __restrict__ g2, const float* __restrict__ be2,
         const float* __restrict__ m2, const float* __restrict__ v2,
         const float* __restrict__ wp2, const float* __restrict__ bp2,
         const float* __restrict__ alpha, int d_base) {
  __shared__ float tile[68 * PITCH];
  __shared__ ull Wsm[25];
  int blk = blockIdx.x;
  int bc = blk >> 3;                 // b*64 + c, 0..255
  int p = bc * 16 + d_base + (blk & 7);
  int c = bc & 63;
  int tid = threadIdx.x;

  if (p == 0) {                      // only in the d_base==0 half, blk 0
    int cc = tid >> 2, j = tid & 3;
    int o0 = 2 * j, o1 = o0 + 1;
    float s2a = __ldg(g2 + o0) * rsqrtf(__ldg(v2 + o0) + EPSBN);
    float s2b = __ldg(g2 + o1) * rsqrtf(__ldg(v2 + o1) + EPSBN);
    g_c2.w1o[cc * 4 + j] = pk(__ldg(wp1 + o0 * 64 + cc) * s2a,
                              __ldg(wp1 + o1 * 64 + cc) * s2b);
    g_c2.w2o[cc * 4 + j] = pk(__ldg(wp2 + cc * 8 + o0), __ldg(wp2 + cc * 8 + o1));
    if (tid < 4) {
      int p0 = 2 * tid, p1 = p0 + 1;
      float sa = __ldg(g2 + p0) * rsqrtf(__ldg(v2 + p0) + EPSBN);
      float sb = __ldg(g2 + p1) * rsqrtf(__ldg(v2 + p1) + EPSBN);
      g_c2.b1o[tid] = pk((__ldg(bp1 + p0) - __ldg(m2 + p0)) * sa + __ldg(be2 + p0),
                         (__ldg(bp1 + p1) - __ldg(m2 + p1)) * sb + __ldg(be2 + p1));
    }
    if (tid < 64) g_c2.b2[tid] = __ldg(bp2 + tid);
    if (tid == 0) g_c2.alpha = __ldg(alpha);
  }

  float t1;
  {
    float s1 = __ldg(g1 + c) * rsqrtf(__ldg(v1 + c) + EPSBN);
    t1 = __ldg(be1 + c) - __ldg(m1 + c) * s1;
    if (tid < 25) {
      float w = __ldg(wdw + c * 25 + tid) * s1;
      Wsm[tid] = pk(w, w);
    }
  }

  // halo-only zeroing
  {
    {
      int i = tid;                     // 0..255
      int r = i / 76, cc2 = i - r * 76;
      int row = (r < 2) ? r : r + 64;
      tile[row * PITCH + cc2] = 0.f;
    }
    if (tid < 48) {
      int i2 = 256 + tid;              // 256..303
      int r = i2 / 76, cc2 = i2 - r * 76;
      int row = (r < 2) ? r : r + 64;
      tile[row * PITCH + cc2] = 0.f;
    }
    {
      int row = 2 + (tid >> 2);        // 2..65
      const int cmap[4] = {0, 1, 66, 67};
      tile[row * PITCH + cmap[tid & 3]] = 0.f;
    }
  }
  __syncthreads();
  const float* xp = x + (size_t)p * 4096;
  #pragma unroll
  for (int it = 0; it < 4; it++) {
    int i = tid + it * 256;
    int h = i >> 4, q = i & 15;
    float4 v = *reinterpret_cast<const float4*>(xp + h * 64 + q * 4);
    float* dst = &tile[(h + 2) * PITCH + q * 4 + 2];
    dst[0] = v.x; dst[1] = v.y; dst[2] = v.z; dst[3] = v.w;
  }
  __syncthreads();

  int wq = (tid & 3) | ((tid >> 1) & 4);           // 0..7
  int hb = ((tid >> 2) & 1) | ((tid >> 3) & 0x1E); // 0..31; rows hb, hb+32

  ull A[8];
  #pragma unroll
  for (int m = 0; m < 8; m++) A[m] = pk(t1, t1);

  #pragma unroll
  for (int r = 0; r < 5; r++) {
    ull W0 = Wsm[5*r+0], W1 = Wsm[5*r+1], W2 = Wsm[5*r+2],
        W3 = Wsm[5*r+3], W4 = Wsm[5*r+4];
    #pragma unroll
    for (int g = 0; g < 2; g++) {
      const float* row = &tile[(hb + 32 * g + r) * PITCH + 8 * wq];
      float4 Q0 = *reinterpret_cast<const float4*>(row);
      float4 Q1 = *reinterpret_cast<const float4*>(row + 4);
      float4 Q2 = *reinterpret_cast<const float4*>(row + 8);
      ull E[6] = {pk(Q0.x, Q0.y), pk(Q0.z, Q0.w), pk(Q1.x, Q1.y),
                  pk(Q1.z, Q1.w), pk(Q2.x, Q2.y), pk(Q2.z, Q2.w)};
      ull O[5] = {pk(Q0.y, Q0.z), pk(Q0.w, Q1.x), pk(Q1.y, Q1.z),
                  pk(Q1.w, Q2.x), pk(Q2.y, Q2.z)};
      #pragma unroll
      for (int m = 0; m < 4; m++) {
        ull a = A[4 * g + m];
        a = fma2(W0, E[m], a);
        a = fma2(W1, O[m], a);
        a = fma2(W2, E[m + 1], a);
        a = fma2(W3, O[m + 1], a);
        a = fma2(W4, E[m + 2], a);
        A[4 * g + m] = a;
      }
    }
  }

  __half* yp = g_y1 + (size_t)p * 4096;
  #pragma unroll
  for (int g = 0; g < 2; g++) {
    int h = hb + 32 * g;
    unsigned hh[4];
    #pragma unroll
    for (int m = 0; m < 4; m++) {
      float a0, a1; upk(a0, a1, A[4 * g + m]);
      __half2 p2 = __floats2half2_rn(silu_f(a0), silu_f(a1));
      hh[m] = *reinterpret_cast<unsigned*>(&p2);
    }
    *reinterpret_cast<uint4*>(yp + h * 64 + 8 * wq) =
        make_uint4(hh[0], hh[1], hh[2], hh[3]);
  }
}

// ---------------- kernel 2: pointwise + attn + top-38 + output ------------
// R15 frozen internals; d_base selects an 8-deep half (512 blocks).
__global__ void __launch_bounds__(256, 4)
k_attn(const float* __restrict__ x, float* __restrict__ out, int d_base) {
  extern __shared__ __half2 park[];         // [32][256] keys = 32KB
  int tid = threadIdx.x;
  int b = blockIdx.x >> 7;                  // 128 blocks per batch
  int rem = blockIdx.x & 127;
  int d = d_base + (rem >> 4);
  int sp = d * 4096 + (rem & 15) * 256 + tid;
  size_t xb = (size_t)b * 4194304 + (size_t)sp;   // + c*65536

  ull h2[4] = {c2.b1o[0], c2.b1o[1], c2.b1o[2], c2.b1o[3]};
  #pragma unroll
  for (int c = 0; c < 64; c++) {
    float xv = __ldg(x + xb + (size_t)c * 65536);
    ull xx = pk(xv, xv);
    #pragma unroll
    for (int j = 0; j < 4; j++) h2[j] = fma2(c2.w1o[c * 4 + j], xx, h2[j]);
  }
  ull hb2[4];
  #pragma unroll
  for (int j = 0; j < 4; j++) {
    float u, v; upk(u, v, h2[j]);
    hb2[j] = pk(silu_f(u), silu_f(v));
  }

  __half2 ph[32];
  __half2* mypark = park + tid;
  #pragma unroll
  for (int i = 0; i < 32; i++) {
    ull accA = pk(c2.b2[i], 0.0f);
    ull accB = pk(c2.b2[i + 32], 0.0f);
    #pragma unroll
    for (int j = 0; j < 4; j++) {
      accA = fma2(c2.w2o[i * 4 + j], hb2[j], accA);
      accB = fma2(c2.w2o[(i + 32) * 4 + j], hb2[j], accB);
    }
    float loA, hiA, loB, hiB;
    upk(loA, hiA, accA); upk(loB, hiB, accB);
    float y1A = __half2float(__ldcs(g_y1 + xb + (size_t)i * 65536));
    float y1B = __half2float(__ldcs(g_y1 + xb + (size_t)(i + 32) * 65536));
    __half2 key = __floats2half2_rn(y1A * (loA + hiA), -(y1B * (loB + hiB)));
    mypark[i * 256] = key;
    ph[i] = key;
  }

  #pragma unroll
  for (int k = 2; k <= 32; k <<= 1) {
    #pragma unroll
    for (int j = k >> 1; j > 0; j >>= 1) {
      #pragma unroll
      for (int i = 0; i < 32; i++) {
        int l = i ^ j;
        if (l > i) {
          __half2 a = ph[i], bz = ph[l];
          __half2 mn = __hmin2(a, bz), mx = __hmax2(a, bz);
          if ((i & k) == 0) { ph[i] = mn; ph[l] = mx; }
          else              { ph[i] = mx; ph[l] = mn; }
        }
      }
    }
  }

  __half2 HV[16];
  #pragma unroll
  for (int k2 = 0; k2 < 16; k2++) {
    __half2 m0 = __hmin2(ph[2 * k2],
                         __hneg2(__lowhigh2highlow(ph[2 * k2])));
    __half2 m1 = __hmin2(ph[2 * k2 + 1],
                         __hneg2(__lowhigh2highlow(ph[2 * k2 + 1])));
    HV[k2] = __halves2half2(__low2half(m0), __low2half(m1));
  }
  #pragma unroll
  for (int i = 0; i < 8; i++) HV[i + 8] = __hmax2(HV[i], HV[i + 8]);
  #pragma unroll
  for (int i = 8; i < 12; i++) HV[i + 4] = __hmax2(HV[i], HV[i + 4]);
  HV[12] = __hmin2(HV[12], HV[14]);
  HV[13] = __hmin2(HV[13], HV[15]);
  HV[13] = __hmax2(HV[12], HV[13]);
  float thr = __half2float(__hmin(__low2half(HV[13]), __high2half(HV[13])));
  float alpha = c2.alpha;

  #pragma unroll
  for (int i = 0; i < 32; i++) {
    __half2 key = mypark[i * 256];
    float2 f = __half22float2(key);
    float aA = f.x, aB = -f.y;
    float xA = __ldg(x + xb + (size_t)i * 65536);
    float xB = __ldg(x + xb + (size_t)(i + 32) * 65536);
    float rA = (aA >= thr) ? fmaf(alpha, aA, xA) : xA;
    float rB = (aB >= thr) ? fmaf(alpha, aB, xB) : xB;
    __stcs(out + xb + (size_t)i * 65536, rA);
    __stcs(out + xb + (size_t)(i + 32) * 65536, rB);
  }
}

// ---------------------------------------------------------------------------
extern "C" void kernel_launch(void* const* d_in, const int* in_sizes, int n_in,
                              void* d_out, int out_size) {
  const float* x    = (const float*)d_in[0];
  const float* wdw  = (const float*)d_in[1];
  const float* g1   = (const float*)d_in[2];
  const float* be1  = (const float*)d_in[3];
  const float* m1   = (const float*)d_in[4];
  const float* v1   = (const float*)d_in[5];
  const float* wp1  = (const float*)d_in[6];
  const float* bp1  = (const float*)d_in[7];
  const float* g2   = (const float*)d_in[8];
  const float* be2  = (const float*)d_in[9];
  const float* m2   = (const float*)d_in[10];
  const float* v2   = (const float*)d_in[11];
  const float* wp2  = (const float*)d_in[12];
  const float* bp2  = (const float*)d_in[13];
  const float* alpha= (const float*)d_in[14];
  float* out = (float*)d_out;

  // side stream + fork/join events, created once on the first (uncaptured)
  // correctness call; reused by the capture call. No device allocation.
  static cudaStream_t s2 = nullptr;
  static cudaEvent_t evF = nullptr, evJ = nullptr;
  if (s2 == nullptr) {
    cudaStreamCreateWithFlags(&s2, cudaStreamNonBlocking);
    cudaEventCreateWithFlags(&evF, cudaEventDisableTiming);
    cudaEventCreateWithFlags(&evJ, cudaEventDisableTiming);
  }

  void* gaddr = nullptr;
  cudaGetSymbolAddress(&gaddr, g_c2);
  cudaFuncSetAttribute(k_attn, cudaFuncAttributeMaxDynamicSharedMemorySize,
                       32768);

  // stream 0: dwconv first half (d 0..7) + param memcpy
  k_dwconv<<<2048, 256>>>(x, wdw, g1, be1, m1, v1, wp1, bp1,
                          g2, be2, m2, v2, wp2, bp2, alpha, 0);
  cudaMemcpyToSymbolAsync(c2, gaddr, sizeof(C2), 0,
                          cudaMemcpyDeviceToDevice, 0);
  cudaEventRecord(evF, 0);

  // stream 0: dwconv second half (d 8..15), concurrent with s2's attn
  k_dwconv<<<2048, 256>>>(x, wdw, g1, be1, m1, v1, wp1, bp1,
                          g2, be2, m2, v2, wp2, bp2, alpha, 8);

  // s2: attn first half after fork
  cudaStreamWaitEvent(s2, evF, 0);
  k_attn<<<512, 256, 32768, s2>>>(x, out, 0);
  cudaEventRecord(evJ, s2);

  // stream 0: join, then attn second half
  cudaStreamWaitEvent(0, evJ, 0);
  k_attn<<<512, 256, 32768>>>(x, out, 8);
}

// round 17
// speedup vs baseline: 1.1292x; 1.1292x over previous
#include <cuda_runtime.h>
#include <cuda_fp16.h>

// B=4, C=64, D=16, H=64, W=64, C8=8, k=38 -> thr = rank-26 ascending of 64
#define EPSBN 1e-5f
typedef unsigned long long ull;

// ---------------- packed f32x2 helpers (fma pipe) ----------------
__device__ __forceinline__ ull pk(float lo, float hi) {
  ull r; asm("mov.b64 %0,{%1,%2};" : "=l"(r) : "f"(lo), "f"(hi)); return r;
}
__device__ __forceinline__ void upk(float& lo, float& hi, ull v) {
  asm("mov.b64 {%0,%1},%2;" : "=f"(lo), "=f"(hi) : "l"(v));
}
__device__ __forceinline__ ull fma2(ull a, ull b, ull c) {
  ull d; asm("fma.rn.f32x2 %0,%1,%2,%3;" : "=l"(d) : "l"(a), "l"(b), "l"(c)); return d;
}
__device__ __forceinline__ float silu_f(float v) {
  return v * (1.0f / (1.0f + __expf(-v)));
}

// ---------------- params ----------------
struct __align__(16) C2 {
  ull w1o[256];   // [c*4+j] = pk(w1t[c][2j], w1t[c][2j+1]), bn2 scale folded
  ull w2o[256];   // [c*4+j] = pk(w2[c][2j], w2[c][2j+1])
  ull b1o[4];     // pk(b1_eff[2j], b1_eff[2j+1])
  float b2[64];
  float alpha;
};
__device__   C2 g_c2;
__constant__ C2 c2;
__device__ __half g_y1[16777216];   // 32MB; linear indexing matches x

// ---------------- kernel 1: depthwise conv + BN + SiLU -> fp16 y1 ----------
// R12/R15 frozen: 8-wide tiles, 3 aligned LDS.128/row, conflict-free lane
// remap, pitch 76, f32x2 accumulation, smem packed weights, halo-only zeroing.
#define PITCH 76
__global__ void __launch_bounds__(256)
k_dwconv(const float* __restrict__ x,
         const float* __restrict__ wdw,
         const float* __restrict__ g1, const float* __restrict__ be1,
         const float* __restrict__ m1, const float* __restrict__ v1,
         const float* __restrict__ wp1, const float* __restrict__ bp1,
         const float* __restrict__ g2, const float* __restrict__ be2,
         const float* __restrict__ m2, const float* __restrict__ v2,
         const float* __restrict__ wp2, const float* __restrict__ bp2,
         const float* __restrict__ alpha) {
  __shared__ float tile[68 * PITCH];
  __shared__ ull Wsm[25];
  int p = blockIdx.x;               // ((b*64+c)*16+d)
  int c = (p >> 4) & 63;
  int tid = threadIdx.x;

  if (p == 0) {
    int cc = tid >> 2, j = tid & 3;
    int o0 = 2 * j, o1 = o0 + 1;
    float s2a = __ldg(g2 + o0) * rsqrtf(__ldg(v2 + o0) + EPSBN);
    float s2b = __ldg(g2 + o1) * rsqrtf(__ldg(v2 + o1) + EPSBN);
    g_c2.w1o[cc * 4 + j] = pk(__ldg(wp1 + o0 * 64 + cc) * s2a,
                              __ldg(wp1 + o1 * 64 + cc) * s2b);
    g_c2.w2o[cc * 4 + j] = pk(__ldg(wp2 + cc * 8 + o0), __ldg(wp2 + cc * 8 + o1));
    if (tid < 4) {
      int p0 = 2 * tid, p1 = p0 + 1;
      float sa = __ldg(g2 + p0) * rsqrtf(__ldg(v2 + p0) + EPSBN);
      float sb = __ldg(g2 + p1) * rsqrtf(__ldg(v2 + p1) + EPSBN);
      g_c2.b1o[tid] = pk((__ldg(bp1 + p0) - __ldg(m2 + p0)) * sa + __ldg(be2 + p0),
                         (__ldg(bp1 + p1) - __ldg(m2 + p1)) * sb + __ldg(be2 + p1));
    }
    if (tid < 64) g_c2.b2[tid] = __ldg(bp2 + tid);
    if (tid == 0) g_c2.alpha = __ldg(alpha);
  }

  float t1;
  {
    float s1 = __ldg(g1 + c) * rsqrtf(__ldg(v1 + c) + EPSBN);
    t1 = __ldg(be1 + c) - __ldg(m1 + c) * s1;
    if (tid < 25) {
      float w = __ldg(wdw + c * 25 + tid) * s1;
      Wsm[tid] = pk(w, w);
    }
  }

  // halo-only zeroing
  {
    {
      int i = tid;                     // 0..255
      int r = i / 76, cc2 = i - r * 76;
      int row = (r < 2) ? r : r + 64;
      tile[row * PITCH + cc2] = 0.f;
    }
    if (tid < 48) {
      int i2 = 256 + tid;              // 256..303
      int r = i2 / 76, cc2 = i2 - r * 76;
      int row = (r < 2) ? r : r + 64;
      tile[row * PITCH + cc2] = 0.f;
    }
    {
      int row = 2 + (tid >> 2);        // 2..65
      const int cmap[4] = {0, 1, 66, 67};
      tile[row * PITCH + cmap[tid & 3]] = 0.f;
    }
  }
  __syncthreads();
  const float* xp = x + (size_t)p * 4096;
  #pragma unroll
  for (int it = 0; it < 4; it++) {
    int i = tid + it * 256;
    int h = i >> 4, q = i & 15;
    float4 v = *reinterpret_cast<const float4*>(xp + h * 64 + q * 4);
    float* dst = &tile[(h + 2) * PITCH + q * 4 + 2];
    dst[0] = v.x; dst[1] = v.y; dst[2] = v.z; dst[3] = v.w;
  }
  __syncthreads();

  int wq = (tid & 3) | ((tid >> 1) & 4);           // 0..7
  int hb = ((tid >> 2) & 1) | ((tid >> 3) & 0x1E); // 0..31; rows hb, hb+32

  ull A[8];
  #pragma unroll
  for (int m = 0; m < 8; m++) A[m] = pk(t1, t1);

  #pragma unroll
  for (int r = 0; r < 5; r++) {
    ull W0 = Wsm[5*r+0], W1 = Wsm[5*r+1], W2 = Wsm[5*r+2],
        W3 = Wsm[5*r+3], W4 = Wsm[5*r+4];
    #pragma unroll
    for (int g = 0; g < 2; g++) {
      const float* row = &tile[(hb + 32 * g + r) * PITCH + 8 * wq];
      float4 Q0 = *reinterpret_cast<const float4*>(row);
      float4 Q1 = *reinterpret_cast<const float4*>(row + 4);
      float4 Q2 = *reinterpret_cast<const float4*>(row + 8);
      ull E[6] = {pk(Q0.x, Q0.y), pk(Q0.z, Q0.w), pk(Q1.x, Q1.y),
                  pk(Q1.z, Q1.w), pk(Q2.x, Q2.y), pk(Q2.z, Q2.w)};
      ull O[5] = {pk(Q0.y, Q0.z), pk(Q0.w, Q1.x), pk(Q1.y, Q1.z),
                  pk(Q1.w, Q2.x), pk(Q2.y, Q2.z)};
      #pragma unroll
      for (int m = 0; m < 4; m++) {
        ull a = A[4 * g + m];
        a = fma2(W0, E[m], a);
        a = fma2(W1, O[m], a);
        a = fma2(W2, E[m + 1], a);
        a = fma2(W3, O[m + 1], a);
        a = fma2(W4, E[m + 2], a);
        A[4 * g + m] = a;
      }
    }
  }

  __half* yp = g_y1 + (size_t)p * 4096;
  #pragma unroll
  for (int g = 0; g < 2; g++) {
    int h = hb + 32 * g;
    unsigned hh[4];
    #pragma unroll
    for (int m = 0; m < 4; m++) {
      float a0, a1; upk(a0, a1, A[4 * g + m]);
      __half2 p2 = __floats2half2_rn(silu_f(a0), silu_f(a1));
      hh[m] = *reinterpret_cast<unsigned*>(&p2);
    }
    *reinterpret_cast<uint4*>(yp + h * 64 + 8 * wq) =
        make_uint4(hh[0], hh[1], hh[2], hh[3]);
  }
}

// ---------------- kernel 2: pointwise + attn + top-38 + output ------------
// R15 internals + LDC.128 weight loads (ulonglong2 casts halve the
// constant-load instruction count in both matvec passes).
__global__ void __launch_bounds__(256, 4)
k_attn(const float* __restrict__ x, float* __restrict__ out) {
  extern __shared__ __half2 park[];         // [32][256] keys = 32KB
  int tid = threadIdx.x;
  int t = blockIdx.x * 256 + tid;
  int b = t >> 16;
  int sp = t & 65535;
  size_t xb = (size_t)b * 4194304 + (size_t)sp;   // + c*65536

  const ulonglong2* w1v = reinterpret_cast<const ulonglong2*>(c2.w1o);
  const ulonglong2* w2v = reinterpret_cast<const ulonglong2*>(c2.w2o);

  ull h2[4] = {c2.b1o[0], c2.b1o[1], c2.b1o[2], c2.b1o[3]};
  #pragma unroll
  for (int c = 0; c < 64; c++) {
    float xv = __ldg(x + xb + (size_t)c * 65536);
    ull xx = pk(xv, xv);
    ulonglong2 Wa = w1v[c * 2];
    ulonglong2 Wb = w1v[c * 2 + 1];
    h2[0] = fma2(Wa.x, xx, h2[0]);
    h2[1] = fma2(Wa.y, xx, h2[1]);
    h2[2] = fma2(Wb.x, xx, h2[2]);
    h2[3] = fma2(Wb.y, xx, h2[3]);
  }
  ull hb2[4];
  #pragma unroll
  for (int j = 0; j < 4; j++) {
    float u, v; upk(u, v, h2[j]);
    hb2[j] = pk(silu_f(u), silu_f(v));
  }

  __half2 ph[32];
  __half2* mypark = park + tid;
  #pragma unroll
  for (int i = 0; i < 32; i++) {
    ull accA = pk(c2.b2[i], 0.0f);
    ull accB = pk(c2.b2[i + 32], 0.0f);
    ulonglong2 Aa = w2v[i * 2],        Ab = w2v[i * 2 + 1];
    ulonglong2 Ba = w2v[(i + 32) * 2], Bb = w2v[(i + 32) * 2 + 1];
    accA = fma2(Aa.x, hb2[0], accA); accA = fma2(Aa.y, hb2[1], accA);
    accA = fma2(Ab.x, hb2[2], accA); accA = fma2(Ab.y, hb2[3], accA);
    accB = fma2(Ba.x, hb2[0], accB); accB = fma2(Ba.y, hb2[1], accB);
    accB = fma2(Bb.x, hb2[2], accB); accB = fma2(Bb.y, hb2[3], accB);
    float loA, hiA, loB, hiB;
    upk(loA, hiA, accA); upk(loB, hiB, accB);
    float y1A = __half2float(__ldcs(g_y1 + xb + (size_t)i * 65536));
    float y1B = __half2float(__ldcs(g_y1 + xb + (size_t)(i + 32) * 65536));
    __half2 key = __floats2half2_rn(y1A * (loA + hiA), -(y1B * (loB + hiB)));
    mypark[i * 256] = key;
    ph[i] = key;
  }

  #pragma unroll
  for (int k = 2; k <= 32; k <<= 1) {
    #pragma unroll
    for (int j = k >> 1; j > 0; j >>= 1) {
      #pragma unroll
      for (int i = 0; i < 32; i++) {
        int l = i ^ j;
        if (l > i) {
          __half2 a = ph[i], bz = ph[l];
          __half2 mn = __hmin2(a, bz), mx = __hmax2(a, bz);
          if ((i & k) == 0) { ph[i] = mn; ph[l] = mx; }
          else              { ph[i] = mx; ph[l] = mn; }
        }
      }
    }
  }

  __half2 HV[16];
  #pragma unroll
  for (int k2 = 0; k2 < 16; k2++) {
    __half2 m0 = __hmin2(ph[2 * k2],
                         __hneg2(__lowhigh2highlow(ph[2 * k2])));
    __half2 m1 = __hmin2(ph[2 * k2 + 1],
                         __hneg2(__lowhigh2highlow(ph[2 * k2 + 1])));
    HV[k2] = __halves2half2(__low2half(m0), __low2half(m1));
  }
  #pragma unroll
  for (int i = 0; i < 8; i++) HV[i + 8] = __hmax2(HV[i], HV[i + 8]);
  #pragma unroll
  for (int i = 8; i < 12; i++) HV[i + 4] = __hmax2(HV[i], HV[i + 4]);
  HV[12] = __hmin2(HV[12], HV[14]);
  HV[13] = __hmin2(HV[13], HV[15]);
  HV[13] = __hmax2(HV[12], HV[13]);
  float thr = __half2float(__hmin(__low2half(HV[13]), __high2half(HV[13])));
  float alpha = c2.alpha;

  #pragma unroll
  for (int i = 0; i < 32; i++) {
    __half2 key = mypark[i * 256];
    float2 f = __half22float2(key);
    float aA = f.x, aB = -f.y;
    float xA = __ldg(x + xb + (size_t)i * 65536);
    float xB = __ldg(x + xb + (size_t)(i + 32) * 65536);
    float rA = (aA >= thr) ? fmaf(alpha, aA, xA) : xA;
    float rB = (aB >= thr) ? fmaf(alpha, aB, xB) : xB;
    __stcs(out + xb + (size_t)i * 65536, rA);
    __stcs(out + xb + (size_t)(i + 32) * 65536, rB);
  }
}

// ---------------------------------------------------------------------------
extern "C" void kernel_launch(void* const* d_in, const int* in_sizes, int n_in,
                              void* d_out, int out_size) {
  const float* x    = (const float*)d_in[0];
  const float* wdw  = (const float*)d_in[1];
  const float* g1   = (const float*)d_in[2];
  const float* be1  = (const float*)d_in[3];
  const float* m1   = (const float*)d_in[4];
  const float* v1   = (const float*)d_in[5];
  const float* wp1  = (const float*)d_in[6];
  const float* bp1  = (const float*)d_in[7];
  const float* g2   = (const float*)d_in[8];
  const float* be2  = (const float*)d_in[9];
  const float* m2   = (const float*)d_in[10];
  const float* v2   = (const float*)d_in[11];
  const float* wp2  = (const float*)d_in[12];
  const float* bp2  = (const float*)d_in[13];
  const float* alpha= (const float*)d_in[14];
  float* out = (float*)d_out;

  k_dwconv<<<4096, 256>>>(x, wdw, g1, be1, m1, v1, wp1, bp1,
                          g2, be2, m2, v2, wp2, bp2, alpha);

  void* gaddr = nullptr;
  cudaGetSymbolAddress(&gaddr, g_c2);
  cudaMemcpyToSymbolAsync(c2, gaddr, sizeof(C2), 0,
                          cudaMemcpyDeviceToDevice, 0);

  cudaFuncSetAttribute(k_attn, cudaFuncAttributeMaxDynamicSharedMemorySize,
                       32768);
  k_attn<<<1024, 256, 32768>>>(x, out);
}